// round 7
// baseline (speedup 1.0000x reference)
#include <cuda_runtime.h>
#include <cuda_bf16.h>
#include <cstdint>

#define DD 256
#define NLIG 2048
#define NPRO 16384
#define NB 32
#define TQA 32
#define TKA 32

__device__ __forceinline__ uint32_t smem_to_u32(const void* p) {
    uint32_t a;
    asm("{ .reg .u64 t; cvta.to.shared.u64 t, %1; cvt.u32.u64 %0, t; }" : "=r"(a) : "l"(p));
    return a;
}

// warp-level bf16 tensor-core MMA (compute_80+; works on plain compute_103)
#define MMA_BF16(c, a, b0v, b1v) \
    asm volatile("mma.sync.aligned.m16n8k16.row.col.f32.bf16.bf16.f32 " \
        "{%0,%1,%2,%3}, {%4,%5,%6,%7}, {%8,%9}, {%0,%1,%2,%3};" \
        : "+f"((c)[0]), "+f"((c)[1]), "+f"((c)[2]), "+f"((c)[3]) \
        : "r"((a)[0]), "r"((a)[1]), "r"((a)[2]), "r"((a)[3]), "r"(b0v), "r"(b1v))

#define LDSM_X4(r, addr) \
    asm volatile("ldmatrix.sync.aligned.m8n8.x4.shared.b16 {%0,%1,%2,%3}, [%4];" \
        : "=r"((r)[0]), "=r"((r)[1]), "=r"((r)[2]), "=r"((r)[3]) : "r"(addr))

// ---------------- scratch (static device allocation; no cudaMalloc) ---------
__device__ float g_Q  [NLIG * DD];
__device__ float g_K  [NPRO * DD];
__device__ float g_V  [NPRO * DD];
__device__ float g_Q2 [NPRO * DD];
__device__ float g_K2 [NLIG * DD];
__device__ float g_V2 [NLIG * DD];
__device__ float g_ctxL[NLIG * DD];
__device__ float g_ctxP[NPRO * DD];
__device__ float g_tmpL[NLIG * DD];
__device__ float g_tmpP[NPRO * DD];
__device__ int g_ls[NB], g_lc[NB], g_ps[NB], g_pc[NB];

// pre-split bf16 hi/lo buffers
__device__ __nv_bfloat16 g_ligH[NLIG * DD], g_ligL[NLIG * DD];
__device__ __nv_bfloat16 g_proH[NPRO * DD], g_proL[NPRO * DD];
__device__ __nv_bfloat16 g_cLH [NLIG * DD], g_cLL [NLIG * DD];
__device__ __nv_bfloat16 g_cPH [NPRO * DD], g_cPL [NPRO * DD];
__device__ __nv_bfloat16 g_WH  [8 * DD * DD], g_WL [8 * DD * DD];

// ---------------- fp32 -> bf16 hi/lo split conversion -----------------------
__device__ __forceinline__ void split2(float a, float b, uint32_t& hi, uint32_t& lo)
{
    __nv_bfloat16 ha = __float2bfloat16(a), hb = __float2bfloat16(b);
    __nv_bfloat162 hp = __halves2bfloat162(ha, hb);
    hi = *reinterpret_cast<uint32_t*>(&hp);
    float la = a - __bfloat162float(ha);
    float lb = b - __bfloat162float(hb);
    __nv_bfloat162 lp = __floats2bfloat162_rn(la, lb);
    lo = *reinterpret_cast<uint32_t*>(&lp);
}

struct ConvOps {
    const float* src[10];
    __nv_bfloat16 *h[10], *l[10];
    int n4[10];
    int nops;
};

__global__ __launch_bounds__(256) void convert_kernel(ConvOps C)
{
    const int op = blockIdx.y;
    const float* __restrict__ s = C.src[op];
    __nv_bfloat16* __restrict__ h = C.h[op];
    __nv_bfloat16* __restrict__ l = C.l[op];
    const int n4 = C.n4[op];
    for (int i = blockIdx.x * 256 + threadIdx.x; i < n4; i += gridDim.x * 256) {
        float4 f = *(const float4*)(s + i * 4);
        uint32_t h0, l0, h1, l1;
        split2(f.x, f.y, h0, l0);
        split2(f.z, f.w, h1, l1);
        *(uint2*)(h + i * 4) = make_uint2(h0, h1);
        *(uint2*)(l + i * 4) = make_uint2(l0, l1);
    }
}

// ---------------- per-batch ranges via binary search (batch ids sorted) -----
__global__ void ranges_kernel(const int* __restrict__ lb, const int* __restrict__ pb)
{
    int t = threadIdx.x;
    if (t < NB) {
        int b = t;
        int lo = 0, hi = NLIG;
        while (lo < hi) { int mid = (lo + hi) >> 1; if (lb[mid] < b) lo = mid + 1; else hi = mid; }
        int s = lo; hi = NLIG;
        while (lo < hi) { int mid = (lo + hi) >> 1; if (lb[mid] <= b) lo = mid + 1; else hi = mid; }
        g_ls[b] = s; g_lc[b] = lo - s;
    } else if (t < 2 * NB) {
        int b = t - NB;
        int lo = 0, hi = NPRO;
        while (lo < hi) { int mid = (lo + hi) >> 1; if (pb[mid] < b) lo = mid + 1; else hi = mid; }
        int s = lo; hi = NPRO;
        while (lo < hi) { int mid = (lo + hi) >> 1; if (pb[mid] <= b) lo = mid + 1; else hi = mid; }
        g_ps[b] = s; g_pc[b] = lo - s;
    }
}

// ============ split-bf16 mma.sync GEMM (pre-split operands) =================
// CTA: 128x128 output, 8 warps (4 M x 2 N), warp tile 32x64, K chunks of 64.
// 3 MMA passes: Ah*Bh + Ah*Bl + Al*Bh (fp32 accum).

struct MmaOps {
    const __nv_bfloat16 *Xh[6], *Xl[6], *Wh[6], *Wl[6];
    float* Y[6];
    int lig_ops;    // first lig_ops ops have 16 row-tiles, remainder 128
};

// smem: A_hi[128][64]bf16 @0, A_lo @16384, B_hi @32768, B_lo @49152
#define GEMM_SMEM 65536

__global__ __launch_bounds__(256, 2) void gemm_mma(MmaOps P)
{
    extern __shared__ char smc[];
    const uint32_t sb = smem_to_u32(smc);

    const int bx = blockIdx.x;
    const int ligregion = P.lig_ops * 16;
    int op, mt;
    if (bx < ligregion) { op = bx >> 4; mt = bx & 15; }
    else { int r = bx - ligregion; op = P.lig_ops + (r >> 7); mt = r & 127; }
    const __nv_bfloat16* __restrict__ Xh = P.Xh[op];
    const __nv_bfloat16* __restrict__ Xl = P.Xl[op];
    const __nv_bfloat16* __restrict__ Wh = P.Wh[op];
    const __nv_bfloat16* __restrict__ Wl = P.Wl[op];
    float* __restrict__ Y = P.Y[op];
    const int m0 = mt * 128;
    const int n0 = blockIdx.y * 128;

    const int tid = threadIdx.x, lane = tid & 31, wid = tid >> 5;
    const int warpM = wid & 3, warpN = wid >> 2;
    const int sub = lane >> 3, r8 = lane & 7;

    float acc[2][8][4];
#pragma unroll
    for (int i = 0; i < 2; ++i)
#pragma unroll
        for (int j = 0; j < 8; ++j)
#pragma unroll
            for (int k = 0; k < 4; ++k) acc[i][j][k] = 0.f;

    for (int kc = 0; kc < 4; ++kc) {
        // ---- stage chunk: straight bf16 copy, 16B-xor swizzled ----
#pragma unroll
        for (int it = 0; it < 4; ++it) {
            int idx = tid + it * 256;       // 0..1023
            int r = idx >> 3, c8 = idx & 7;
            int byte = (r * 128 + c8 * 16) ^ ((r & 7) << 4);
            size_t goff = (size_t)(m0 + r) * DD + kc * 64 + c8 * 8;
            size_t woff = (size_t)(n0 + r) * DD + kc * 64 + c8 * 8;
            *(uint4*)(smc + byte)         = *(const uint4*)(Xh + goff);
            *(uint4*)(smc + 16384 + byte) = *(const uint4*)(Xl + goff);
            *(uint4*)(smc + 32768 + byte) = *(const uint4*)(Wh + woff);
            *(uint4*)(smc + 49152 + byte) = *(const uint4*)(Wl + woff);
        }
        __syncthreads();

#pragma unroll
        for (int k16 = 0; k16 < 4; ++k16) {
            uint32_t a_hi[2][4], a_lo[2][4];
#pragma unroll
            for (int mt2 = 0; mt2 < 2; ++mt2) {
                int row = warpM * 32 + mt2 * 16 + (sub & 1) * 8 + r8;
                int k8  = k16 * 2 + (sub >> 1);
                uint32_t ad = sb + ((row * 128 + k8 * 16) ^ ((row & 7) << 4));
                LDSM_X4(a_hi[mt2], ad);
                LDSM_X4(a_lo[mt2], ad + 16384);
            }
#pragma unroll
            for (int np = 0; np < 4; ++np) {
                int nrow = warpN * 64 + np * 16 + (sub >> 1) * 8 + r8;
                int k8   = k16 * 2 + (sub & 1);
                uint32_t bd = sb + 32768 + ((nrow * 128 + k8 * 16) ^ ((nrow & 7) << 4));
                uint32_t b_hi[4], b_lo[4];
                LDSM_X4(b_hi, bd);
                LDSM_X4(b_lo, bd + 16384);
#pragma unroll
                for (int mt2 = 0; mt2 < 2; ++mt2) {
                    MMA_BF16(acc[mt2][np * 2],     a_hi[mt2], b_hi[0], b_hi[1]);
                    MMA_BF16(acc[mt2][np * 2 + 1], a_hi[mt2], b_hi[2], b_hi[3]);
                    MMA_BF16(acc[mt2][np * 2],     a_hi[mt2], b_lo[0], b_lo[1]);
                    MMA_BF16(acc[mt2][np * 2 + 1], a_hi[mt2], b_lo[2], b_lo[3]);
                    MMA_BF16(acc[mt2][np * 2],     a_lo[mt2], b_hi[0], b_hi[1]);
                    MMA_BF16(acc[mt2][np * 2 + 1], a_lo[mt2], b_hi[2], b_hi[3]);
                }
            }
        }
        __syncthreads();
    }

    // ---- epilogue: fragment -> GMEM ----
    const int t4 = lane >> 2, q = lane & 3;
#pragma unroll
    for (int mt2 = 0; mt2 < 2; ++mt2) {
#pragma unroll
        for (int nt = 0; nt < 8; ++nt) {
            float* yr = Y + (size_t)(m0 + warpM * 32 + mt2 * 16 + t4) * DD
                          + n0 + warpN * 64 + nt * 8 + q * 2;
            *(float2*)yr            = make_float2(acc[mt2][nt][0], acc[mt2][nt][1]);
            *(float2*)(yr + 8 * DD) = make_float2(acc[mt2][nt][2], acc[mt2][nt][3]);
        }
    }
}

// ======== tiled flash attention, block-diagonal mask, no-max softmax ========
// TQA=32 queries/CTA, 8 warps x 4 query rows; lane owns one key per chunk.
// scores bounded (|s| <~ 7) so exp never overflows: no online max needed.

struct AttnSide {
    const float *Q, *K, *V, *qpos, *kpos;
    const int *qbatch, *kbatch, *kstart, *kcount;
    float* ctx;
    int nblk;
};

#define ATTN_SMEM_FLOATS (TQA*256 + 32*256 + 32*256 + TQA*36 + TQA*4 + 32*4 + TQA + 32)
#define ATTN_SMEM_BYTES  (ATTN_SMEM_FLOATS * 4)

__global__ __launch_bounds__(256, 2) void attn_tiled(AttnSide A0, AttnSide A1)
{
    extern __shared__ float sm[];
    float* Qs = sm;                      // [32][256]
    float* Ks = Qs + TQA * 256;          // [32][256] (col4 xor-swizzled by row&7)
    float* Vs = Ks + 32 * 256;           // [32][256]
    float* Ps = Vs + 32 * 256;           // [32][36]
    float* qp = Ps + TQA * 36;           // [32][4]
    float* kp = qp + TQA * 4;            // [32][4]
    int*   qb = (int*)(kp + 32 * 4);     // [32]
    int*   kb = qb + TQA;                // [32]

    const bool first = (blockIdx.x < (unsigned)A0.nblk);
    AttnSide S = first ? A0 : A1;
    const int blk = first ? blockIdx.x : (blockIdx.x - A0.nblk);

    const int tid  = threadIdx.x;
    const int warp = tid >> 5;
    const int lane = tid & 31;
    const int q0   = blk * TQA;

    for (int i = tid; i < TQA * 64; i += 256) {
        int r = i >> 6, c4 = i & 63;
        float4 v = *(const float4*)(S.Q + (size_t)(q0 + r) * DD + c4 * 4);
        v.x *= 0.0625f; v.y *= 0.0625f; v.z *= 0.0625f; v.w *= 0.0625f;
        *(float4*)(Qs + r * 256 + c4 * 4) = v;
    }
    if (tid < TQA) {
        int r = q0 + tid;
        qb[tid] = S.qbatch[r];
        qp[tid * 4 + 0] = S.qpos[r * 3 + 0];
        qp[tid * 4 + 1] = S.qpos[r * 3 + 1];
        qp[tid * 4 + 2] = S.qpos[r * 3 + 2];
    }
    __syncthreads();

    const int js = S.kstart[qb[0]];
    const int b1 = qb[TQA - 1];
    const int je = S.kstart[b1] + S.kcount[b1];

    const int qr = warp * 4;
    float l[4] = {0.f, 0.f, 0.f, 0.f};
    float4 oa[4], ob[4];
#pragma unroll
    for (int i = 0; i < 4; ++i) { oa[i] = make_float4(0,0,0,0); ob[i] = oa[i]; }

    const float* Qb = Qs + qr * 256;
    float qpx[4], qpy[4], qpz[4];
    int qbv[4];
#pragma unroll
    for (int i = 0; i < 4; ++i) {
        qpx[i] = qp[(qr + i) * 4 + 0];
        qpy[i] = qp[(qr + i) * 4 + 1];
        qpz[i] = qp[(qr + i) * 4 + 2];
        qbv[i] = qb[qr + i];
    }

    for (int j0 = js; j0 < je; j0 += TKA) {
        __syncthreads();

        for (int i = tid; i < 32 * 64; i += 256) {
            int r = i >> 6, c4 = i & 63;
            int gj = j0 + r;
            float4 kv = make_float4(0,0,0,0), vv = kv;
            if (gj < je) {
                kv = *(const float4*)(S.K + (size_t)gj * DD + c4 * 4);
                vv = *(const float4*)(S.V + (size_t)gj * DD + c4 * 4);
            }
            *(float4*)(Ks + r * 256 + ((c4 ^ (r & 7)) << 2)) = kv;
            *(float4*)(Vs + r * 256 + (c4 << 2)) = vv;
        }
        if (tid < 32) {
            int gj = j0 + tid;
            if (gj < je) {
                kb[tid] = S.kbatch[gj];
                kp[tid * 4 + 0] = S.kpos[gj * 3 + 0];
                kp[tid * 4 + 1] = S.kpos[gj * 3 + 1];
                kp[tid * 4 + 2] = S.kpos[gj * 3 + 2];
            } else {
                kb[tid] = -1;
                kp[tid * 4 + 0] = 0.f; kp[tid * 4 + 1] = 0.f; kp[tid * 4 + 2] = 0.f;
            }
        }
        __syncthreads();

        // phase A: lane's key vs warp's 4 query rows
        const int   kbj = kb[lane];
        const float kpx = kp[lane * 4 + 0];
        const float kpy = kp[lane * 4 + 1];
        const float kpz = kp[lane * 4 + 2];
        const float* Kr = Ks + lane * 256;
        const int sw = lane & 7;

        float s[4] = {0.f, 0.f, 0.f, 0.f};
#pragma unroll 8
        for (int k4 = 0; k4 < 64; ++k4) {
            float4 kv = *(const float4*)(Kr + ((k4 ^ sw) << 2));
#pragma unroll
            for (int i = 0; i < 4; ++i) {
                float4 qv = *(const float4*)(Qb + i * 256 + k4 * 4);
                s[i] = fmaf(qv.x, kv.x, s[i]); s[i] = fmaf(qv.y, kv.y, s[i]);
                s[i] = fmaf(qv.z, kv.z, s[i]); s[i] = fmaf(qv.w, kv.w, s[i]);
            }
        }

#pragma unroll
        for (int i = 0; i < 4; ++i) {
            float dx = qpx[i] - kpx, dy = qpy[i] - kpy, dz = qpz[i] - kpz;
            float d2 = fmaxf(fmaf(dx, dx, fmaf(dy, dy, dz * dz)), 1e-12f);
            float p = (qbv[i] == kbj) ? __expf(s[i] + __expf(-0.1f * sqrtf(d2))) : 0.f;
            l[i] += p;
            Ps[(qr + i) * 36 + lane] = p;
        }
        __syncwarp();

        // phase B: O += P @ V (rank-32 update, 4 rows share V loads)
#pragma unroll
        for (int j4 = 0; j4 < 8; ++j4) {
            float4 pv[4];
#pragma unroll
            for (int i = 0; i < 4; ++i)
                pv[i] = *(const float4*)(Ps + (qr + i) * 36 + j4 * 4);
#pragma unroll
            for (int jj = 0; jj < 4; ++jj) {
                const float* Vr = Vs + (j4 * 4 + jj) * 256;
                float4 va = *(const float4*)(Vr + lane * 4);
                float4 vb = *(const float4*)(Vr + 128 + lane * 4);
#pragma unroll
                for (int i = 0; i < 4; ++i) {
                    float pa = (&pv[i].x)[jj];
                    oa[i].x = fmaf(pa, va.x, oa[i].x); oa[i].y = fmaf(pa, va.y, oa[i].y);
                    oa[i].z = fmaf(pa, va.z, oa[i].z); oa[i].w = fmaf(pa, va.w, oa[i].w);
                    ob[i].x = fmaf(pa, vb.x, ob[i].x); ob[i].y = fmaf(pa, vb.y, ob[i].y);
                    ob[i].z = fmaf(pa, vb.z, ob[i].z); ob[i].w = fmaf(pa, vb.w, ob[i].w);
                }
            }
        }
    }

    // reduce per-lane sums, normalize, write
#pragma unroll
    for (int i = 0; i < 4; ++i) {
        float li = l[i];
#pragma unroll
        for (int off = 16; off; off >>= 1) li += __shfl_xor_sync(0xffffffffu, li, off);
        float inv = 1.0f / li;
        oa[i].x *= inv; oa[i].y *= inv; oa[i].z *= inv; oa[i].w *= inv;
        ob[i].x *= inv; ob[i].y *= inv; ob[i].z *= inv; ob[i].w *= inv;
        float* c = S.ctx + (size_t)(q0 + qr + i) * DD;
        *(float4*)(c + lane * 4)       = oa[i];
        *(float4*)(c + 128 + lane * 4) = ob[i];
    }
}

// ---------------- residual + bias + layernorm (both sides, one launch) ------
__global__ __launch_bounds__(128) void ln2_kernel(
    const float* __restrict__ lig, const float* __restrict__ pro,
    const float* __restrict__ tL, const float* __restrict__ tP,
    const float* __restrict__ boutL, const float* __restrict__ boutP,
    const float* __restrict__ gL, const float* __restrict__ bL,
    const float* __restrict__ gP, const float* __restrict__ bP,
    float* __restrict__ out)
{
    const int row = blockIdx.x * 4 + (threadIdx.x >> 5);
    const int lane = threadIdx.x & 31;

    const float *x, *y, *bias, *g, *bb;
    if (row < NLIG) {
        x = lig + (size_t)row * DD; y = tL + (size_t)row * DD;
        bias = boutL; g = gL; bb = bL;
    } else {
        int r = row - NLIG;
        x = pro + (size_t)r * DD; y = tP + (size_t)r * DD;
        bias = boutP; g = gP; bb = bP;
    }

    float t[8];
#pragma unroll
    for (int i = 0; i < 8; ++i) {
        int c = lane * 8 + i;
        t[i] = x[c] + y[c] + bias[c];
    }
    float s = 0.f;
#pragma unroll
    for (int i = 0; i < 8; ++i) s += t[i];
#pragma unroll
    for (int off = 16; off; off >>= 1) s += __shfl_xor_sync(0xffffffffu, s, off);
    float mu = s * (1.0f / DD);

    float v = 0.f;
#pragma unroll
    for (int i = 0; i < 8; ++i) { float d = t[i] - mu; v += d * d; }
#pragma unroll
    for (int off = 16; off; off >>= 1) v += __shfl_xor_sync(0xffffffffu, v, off);
    float r = rsqrtf(v * (1.0f / DD) + 1e-5f);

#pragma unroll
    for (int i = 0; i < 8; ++i) {
        int c = lane * 8 + i;
        out[(size_t)row * DD + c] = (t[i] - mu) * r * g[c] + bb[c];
    }
}

// ---------------- launch ----------------------------------------------------
extern "C" void kernel_launch(void* const* d_in, const int* in_sizes, int n_in,
                              void* d_out, int out_size)
{
    const float* lig      = (const float*)d_in[0];
    const float* pro      = (const float*)d_in[1];
    const float* lig_pos  = (const float*)d_in[2];
    const float* pro_pos  = (const float*)d_in[3];
    const int*   lig_batch= (const int*)  d_in[4];
    const int*   pro_batch= (const int*)  d_in[5];
    const float* Wq_lig   = (const float*)d_in[6];
    const float* Wk_pro   = (const float*)d_in[7];
    const float* Wv_pro   = (const float*)d_in[8];
    const float* Wq_pro   = (const float*)d_in[9];
    const float* Wk_lig   = (const float*)d_in[10];
    const float* Wv_lig   = (const float*)d_in[11];
    const float* Wout_lig = (const float*)d_in[12];
    const float* bout_lig = (const float*)d_in[13];
    const float* Wout_pro = (const float*)d_in[14];
    const float* bout_pro = (const float*)d_in[15];
    const float* gl       = (const float*)d_in[16];
    const float* bl       = (const float*)d_in[17];
    const float* gp       = (const float*)d_in[18];
    const float* bp       = (const float*)d_in[19];
    float* out = (float*)d_out;

    float *Q, *K, *V, *Q2, *K2, *V2, *ctxL, *ctxP, *tmpL, *tmpP;
    int *ls, *lc, *ps, *pc;
    __nv_bfloat16 *ligH, *ligL, *proH, *proL, *cLH, *cLL, *cPH, *cPL, *WH, *WL;
    cudaGetSymbolAddress((void**)&Q,    g_Q);
    cudaGetSymbolAddress((void**)&K,    g_K);
    cudaGetSymbolAddress((void**)&V,    g_V);
    cudaGetSymbolAddress((void**)&Q2,   g_Q2);
    cudaGetSymbolAddress((void**)&K2,   g_K2);
    cudaGetSymbolAddress((void**)&V2,   g_V2);
    cudaGetSymbolAddress((void**)&ctxL, g_ctxL);
    cudaGetSymbolAddress((void**)&ctxP, g_ctxP);
    cudaGetSymbolAddress((void**)&tmpL, g_tmpL);
    cudaGetSymbolAddress((void**)&tmpP, g_tmpP);
    cudaGetSymbolAddress((void**)&ls,   g_ls);
    cudaGetSymbolAddress((void**)&lc,   g_lc);
    cudaGetSymbolAddress((void**)&ps,   g_ps);
    cudaGetSymbolAddress((void**)&pc,   g_pc);
    cudaGetSymbolAddress((void**)&ligH, g_ligH);
    cudaGetSymbolAddress((void**)&ligL, g_ligL);
    cudaGetSymbolAddress((void**)&proH, g_proH);
    cudaGetSymbolAddress((void**)&proL, g_proL);
    cudaGetSymbolAddress((void**)&cLH,  g_cLH);
    cudaGetSymbolAddress((void**)&cLL,  g_cLL);
    cudaGetSymbolAddress((void**)&cPH,  g_cPH);
    cudaGetSymbolAddress((void**)&cPL,  g_cPL);
    cudaGetSymbolAddress((void**)&WH,   g_WH);
    cudaGetSymbolAddress((void**)&WL,   g_WL);

    cudaFuncSetAttribute(gemm_mma, cudaFuncAttributeMaxDynamicSharedMemorySize, GEMM_SMEM);
    cudaFuncSetAttribute(attn_tiled, cudaFuncAttributeMaxDynamicSharedMemorySize, ATTN_SMEM_BYTES);

    ranges_kernel<<<1, 64>>>(lig_batch, pro_batch);

    // phase-1 conversion: inputs + all 8 weights
    // weight slots: 0 Wq_lig 1 Wk_lig 2 Wv_lig 3 Wk_pro 4 Wv_pro 5 Wq_pro 6 Wout_lig 7 Wout_pro
    const float* Wsrc[8] = {Wq_lig, Wk_lig, Wv_lig, Wk_pro, Wv_pro, Wq_pro, Wout_lig, Wout_pro};
    ConvOps c1;
    c1.src[0] = lig; c1.h[0] = ligH; c1.l[0] = ligL; c1.n4[0] = NLIG * DD / 4;
    c1.src[1] = pro; c1.h[1] = proH; c1.l[1] = proL; c1.n4[1] = NPRO * DD / 4;
    for (int i = 0; i < 8; ++i) {
        c1.src[2 + i] = Wsrc[i];
        c1.h[2 + i] = WH + i * DD * DD;
        c1.l[2 + i] = WL + i * DD * DD;
        c1.n4[2 + i] = DD * DD / 4;
    }
    c1.nops = 10;
    convert_kernel<<<dim3(128, 10), 256>>>(c1);

    // all 6 QKV projections, one launch: ops 0-2 lig (16 tiles), 3-5 pro (128)
    MmaOps gq;
    const int wmap[6] = {0, 1, 2, 3, 4, 5};
    for (int i = 0; i < 3; ++i) { gq.Xh[i] = ligH; gq.Xl[i] = ligL; }
    for (int i = 3; i < 6; ++i) { gq.Xh[i] = proH; gq.Xl[i] = proL; }
    for (int i = 0; i < 6; ++i) {
        gq.Wh[i] = WH + wmap[i] * DD * DD;
        gq.Wl[i] = WL + wmap[i] * DD * DD;
    }
    gq.Y[0] = Q;  gq.Y[1] = K2; gq.Y[2] = V2;
    gq.Y[3] = K;  gq.Y[4] = V;  gq.Y[5] = Q2;
    gq.lig_ops = 3;
    gemm_mma<<<dim3(3 * 16 + 3 * 128, 2), 256, GEMM_SMEM>>>(gq);

    // both attention directions, one launch (long lig blocks first)
    AttnSide aL, aP;
    aL.Q = Q;  aL.K = K;  aL.V = V;  aL.qpos = lig_pos; aL.kpos = pro_pos;
    aL.qbatch = lig_batch; aL.kbatch = pro_batch; aL.kstart = ps; aL.kcount = pc;
    aL.ctx = ctxL; aL.nblk = NLIG / TQA;
    aP.Q = Q2; aP.K = K2; aP.V = V2; aP.qpos = pro_pos; aP.kpos = lig_pos;
    aP.qbatch = pro_batch; aP.kbatch = lig_batch; aP.kstart = ls; aP.kcount = lc;
    aP.ctx = ctxP; aP.nblk = NPRO / TQA;
    attn_tiled<<<NLIG / TQA + NPRO / TQA, 256, ATTN_SMEM_BYTES>>>(aL, aP);

    // phase-2 conversion: ctx
    ConvOps c2;
    c2.src[0] = ctxL; c2.h[0] = cLH; c2.l[0] = cLL; c2.n4[0] = NLIG * DD / 4;
    c2.src[1] = ctxP; c2.h[1] = cPH; c2.l[1] = cPL; c2.n4[1] = NPRO * DD / 4;
    c2.nops = 2;
    convert_kernel<<<dim3(128, 2), 256>>>(c2);

    // both output projections, one launch
    MmaOps go;
    go.Xh[0] = cLH; go.Xl[0] = cLL;
    go.Xh[1] = cPH; go.Xl[1] = cPL;
    go.Wh[0] = WH + 6 * DD * DD; go.Wl[0] = WL + 6 * DD * DD;
    go.Wh[1] = WH + 7 * DD * DD; go.Wl[1] = WL + 7 * DD * DD;
    go.Y[0] = tmpL; go.Y[1] = tmpP;
    for (int i = 2; i < 6; ++i) {
        go.Xh[i] = cLH; go.Xl[i] = cLL;
        go.Wh[i] = WH + 6 * DD * DD; go.Wl[i] = WL + 6 * DD * DD;
        go.Y[i] = tmpL;
    }
    go.lig_ops = 1;
    gemm_mma<<<dim3(16 + 128, 2), 256, GEMM_SMEM>>>(go);

    // both layernorms, one launch
    ln2_kernel<<<(NLIG + NPRO) / 4, 128>>>(lig, pro, tmpL, tmpP,
                                           bout_lig, bout_pro, gl, bl, gp, bp, out);
}

// round 8
// speedup vs baseline: 1.3382x; 1.3382x over previous
#include <cuda_runtime.h>
#include <cuda_bf16.h>
#include <cstdint>

#define DD 256
#define NLIG 2048
#define NPRO 16384
#define NB 32
#define TQA 32
#define TKA 32
#define SPLITS 4

__device__ __forceinline__ uint32_t smem_to_u32(const void* p) {
    uint32_t a;
    asm("{ .reg .u64 t; cvta.to.shared.u64 t, %1; cvt.u32.u64 %0, t; }" : "=r"(a) : "l"(p));
    return a;
}

// warp-level bf16 tensor-core MMA (compute_80+; works on plain compute_103)
#define MMA_BF16(c, a, b0v, b1v) \
    asm volatile("mma.sync.aligned.m16n8k16.row.col.f32.bf16.bf16.f32 " \
        "{%0,%1,%2,%3}, {%4,%5,%6,%7}, {%8,%9}, {%0,%1,%2,%3};" \
        : "+f"((c)[0]), "+f"((c)[1]), "+f"((c)[2]), "+f"((c)[3]) \
        : "r"((a)[0]), "r"((a)[1]), "r"((a)[2]), "r"((a)[3]), "r"(b0v), "r"(b1v))

#define LDSM_X4(r, addr) \
    asm volatile("ldmatrix.sync.aligned.m8n8.x4.shared.b16 {%0,%1,%2,%3}, [%4];" \
        : "=r"((r)[0]), "=r"((r)[1]), "=r"((r)[2]), "=r"((r)[3]) : "r"(addr))

// ---------------- scratch (static device allocation; no cudaMalloc) ---------
__device__ float g_Q  [NLIG * DD];
__device__ float g_K  [NPRO * DD];
__device__ float g_V  [NPRO * DD];
__device__ float g_Q2 [NPRO * DD];
__device__ float g_K2 [NLIG * DD];
__device__ float g_V2 [NLIG * DD];
__device__ float g_ctxL[NLIG * DD];
__device__ float g_ctxP[NPRO * DD];
__device__ float g_tmpL[NLIG * DD];
__device__ float g_tmpP[NPRO * DD];
__device__ float g_ctxLp[SPLITS * NLIG * DD];   // lig split-K partials
__device__ float g_denLp[SPLITS * NLIG];        // lig split-K denominators
__device__ int g_ls[NB], g_lc[NB], g_ps[NB], g_pc[NB];

// pre-split bf16 hi/lo buffers
__device__ __nv_bfloat16 g_ligH[NLIG * DD], g_ligL[NLIG * DD];
__device__ __nv_bfloat16 g_proH[NPRO * DD], g_proL[NPRO * DD];
__device__ __nv_bfloat16 g_cLH [NLIG * DD], g_cLL [NLIG * DD];
__device__ __nv_bfloat16 g_cPH [NPRO * DD], g_cPL [NPRO * DD];
__device__ __nv_bfloat16 g_WH  [8 * DD * DD], g_WL [8 * DD * DD];

// ---------------- fp32 -> bf16 hi/lo split conversion -----------------------
__device__ __forceinline__ void split2(float a, float b, uint32_t& hi, uint32_t& lo)
{
    __nv_bfloat16 ha = __float2bfloat16(a), hb = __float2bfloat16(b);
    __nv_bfloat162 hp = __halves2bfloat162(ha, hb);
    hi = *reinterpret_cast<uint32_t*>(&hp);
    float la = a - __bfloat162float(ha);
    float lb = b - __bfloat162float(hb);
    __nv_bfloat162 lp = __floats2bfloat162_rn(la, lb);
    lo = *reinterpret_cast<uint32_t*>(&lp);
}

struct ConvOps {
    const float* src[10];
    __nv_bfloat16 *h[10], *l[10];
    int n4[10];
    int nops;
};

__global__ __launch_bounds__(256) void convert_kernel(ConvOps C)
{
    const int op = blockIdx.y;
    const float* __restrict__ s = C.src[op];
    __nv_bfloat16* __restrict__ h = C.h[op];
    __nv_bfloat16* __restrict__ l = C.l[op];
    const int n4 = C.n4[op];
    for (int i = blockIdx.x * 256 + threadIdx.x; i < n4; i += gridDim.x * 256) {
        float4 f = *(const float4*)(s + i * 4);
        uint32_t h0, l0, h1, l1;
        split2(f.x, f.y, h0, l0);
        split2(f.z, f.w, h1, l1);
        *(uint2*)(h + i * 4) = make_uint2(h0, h1);
        *(uint2*)(l + i * 4) = make_uint2(l0, l1);
    }
}

// ---------------- per-batch ranges via binary search (batch ids sorted) -----
__global__ void ranges_kernel(const int* __restrict__ lb, const int* __restrict__ pb)
{
    int t = threadIdx.x;
    if (t < NB) {
        int b = t;
        int lo = 0, hi = NLIG;
        while (lo < hi) { int mid = (lo + hi) >> 1; if (lb[mid] < b) lo = mid + 1; else hi = mid; }
        int s = lo; hi = NLIG;
        while (lo < hi) { int mid = (lo + hi) >> 1; if (lb[mid] <= b) lo = mid + 1; else hi = mid; }
        g_ls[b] = s; g_lc[b] = lo - s;
    } else if (t < 2 * NB) {
        int b = t - NB;
        int lo = 0, hi = NPRO;
        while (lo < hi) { int mid = (lo + hi) >> 1; if (pb[mid] < b) lo = mid + 1; else hi = mid; }
        int s = lo; hi = NPRO;
        while (lo < hi) { int mid = (lo + hi) >> 1; if (pb[mid] <= b) lo = mid + 1; else hi = mid; }
        g_ps[b] = s; g_pc[b] = lo - s;
    }
}

// ============ split-bf16 mma.sync GEMM (pre-split operands) =================
struct MmaOps {
    const __nv_bfloat16 *Xh[6], *Xl[6], *Wh[6], *Wl[6];
    float* Y[6];
    int lig_ops;    // first lig_ops ops have 16 row-tiles, remainder 128
};

#define GEMM_SMEM 65536

__global__ __launch_bounds__(256, 2) void gemm_mma(MmaOps P)
{
    extern __shared__ char smc[];
    const uint32_t sb = smem_to_u32(smc);

    const int bx = blockIdx.x;
    const int ligregion = P.lig_ops * 16;
    int op, mt;
    if (bx < ligregion) { op = bx >> 4; mt = bx & 15; }
    else { int r = bx - ligregion; op = P.lig_ops + (r >> 7); mt = r & 127; }
    const __nv_bfloat16* __restrict__ Xh = P.Xh[op];
    const __nv_bfloat16* __restrict__ Xl = P.Xl[op];
    const __nv_bfloat16* __restrict__ Wh = P.Wh[op];
    const __nv_bfloat16* __restrict__ Wl = P.Wl[op];
    float* __restrict__ Y = P.Y[op];
    const int m0 = mt * 128;
    const int n0 = blockIdx.y * 128;

    const int tid = threadIdx.x, lane = tid & 31, wid = tid >> 5;
    const int warpM = wid & 3, warpN = wid >> 2;
    const int sub = lane >> 3, r8 = lane & 7;

    float acc[2][8][4];
#pragma unroll
    for (int i = 0; i < 2; ++i)
#pragma unroll
        for (int j = 0; j < 8; ++j)
#pragma unroll
            for (int k = 0; k < 4; ++k) acc[i][j][k] = 0.f;

    for (int kc = 0; kc < 4; ++kc) {
#pragma unroll
        for (int it = 0; it < 4; ++it) {
            int idx = tid + it * 256;
            int r = idx >> 3, c8 = idx & 7;
            int byte = (r * 128 + c8 * 16) ^ ((r & 7) << 4);
            size_t goff = (size_t)(m0 + r) * DD + kc * 64 + c8 * 8;
            size_t woff = (size_t)(n0 + r) * DD + kc * 64 + c8 * 8;
            *(uint4*)(smc + byte)         = *(const uint4*)(Xh + goff);
            *(uint4*)(smc + 16384 + byte) = *(const uint4*)(Xl + goff);
            *(uint4*)(smc + 32768 + byte) = *(const uint4*)(Wh + woff);
            *(uint4*)(smc + 49152 + byte) = *(const uint4*)(Wl + woff);
        }
        __syncthreads();

#pragma unroll
        for (int k16 = 0; k16 < 4; ++k16) {
            uint32_t a_hi[2][4], a_lo[2][4];
#pragma unroll
            for (int mt2 = 0; mt2 < 2; ++mt2) {
                int row = warpM * 32 + mt2 * 16 + (sub & 1) * 8 + r8;
                int k8  = k16 * 2 + (sub >> 1);
                uint32_t ad = sb + ((row * 128 + k8 * 16) ^ ((row & 7) << 4));
                LDSM_X4(a_hi[mt2], ad);
                LDSM_X4(a_lo[mt2], ad + 16384);
            }
#pragma unroll
            for (int np = 0; np < 4; ++np) {
                int nrow = warpN * 64 + np * 16 + (sub >> 1) * 8 + r8;
                int k8   = k16 * 2 + (sub & 1);
                uint32_t bd = sb + 32768 + ((nrow * 128 + k8 * 16) ^ ((nrow & 7) << 4));
                uint32_t b_hi[4], b_lo[4];
                LDSM_X4(b_hi, bd);
                LDSM_X4(b_lo, bd + 16384);
#pragma unroll
                for (int mt2 = 0; mt2 < 2; ++mt2) {
                    MMA_BF16(acc[mt2][np * 2],     a_hi[mt2], b_hi[0], b_hi[1]);
                    MMA_BF16(acc[mt2][np * 2 + 1], a_hi[mt2], b_hi[2], b_hi[3]);
                    MMA_BF16(acc[mt2][np * 2],     a_hi[mt2], b_lo[0], b_lo[1]);
                    MMA_BF16(acc[mt2][np * 2 + 1], a_hi[mt2], b_lo[2], b_lo[3]);
                    MMA_BF16(acc[mt2][np * 2],     a_lo[mt2], b_hi[0], b_hi[1]);
                    MMA_BF16(acc[mt2][np * 2 + 1], a_lo[mt2], b_hi[2], b_hi[3]);
                }
            }
        }
        __syncthreads();
    }

    const int t4 = lane >> 2, q = lane & 3;
#pragma unroll
    for (int mt2 = 0; mt2 < 2; ++mt2) {
#pragma unroll
        for (int nt = 0; nt < 8; ++nt) {
            float* yr = Y + (size_t)(m0 + warpM * 32 + mt2 * 16 + t4) * DD
                          + n0 + warpN * 64 + nt * 8 + q * 2;
            *(float2*)yr            = make_float2(acc[mt2][nt][0], acc[mt2][nt][1]);
            *(float2*)(yr + 8 * DD) = make_float2(acc[mt2][nt][2], acc[mt2][nt][3]);
        }
    }
}

// ======== tiled flash attention, block-diagonal, no-max, split-K ============
// TQA=32 queries/CTA, 8 warps x 4 query rows. Side 0 (lig) splits its key
// range into SPLITS sub-blocks writing additive partials (no-max softmax is
// linear in (sum pV, sum p)); side 1 (pro) normalizes in-kernel.

struct AttnSide {
    const float *Q, *K, *V, *qpos, *kpos;
    const int *qbatch, *kbatch, *kstart, *kcount;
    float* ctx;     // nsplit==1: final ctx; else partials [nsplit][prows][DD]
    float* den;     // nsplit>1: [nsplit][prows]
    int nblk;
    int nsplit;
    int prows;
};

#define ATTN_SMEM_FLOATS (TQA*256 + 32*256 + 32*256 + TQA*36 + TQA*4 + 32*4 + TQA + 32)
#define ATTN_SMEM_BYTES  (ATTN_SMEM_FLOATS * 4)

__global__ __launch_bounds__(256, 2) void attn_tiled(AttnSide A0, AttnSide A1)
{
    extern __shared__ float sm[];
    float* Qs = sm;                      // [32][256]
    float* Ks = Qs + TQA * 256;          // [32][256] (col4 xor-swizzled by row&7)
    float* Vs = Ks + 32 * 256;           // [32][256]
    float* Ps = Vs + 32 * 256;           // [32][36]
    float* qp = Ps + TQA * 36;           // [32][4]
    float* kp = qp + TQA * 4;            // [32][4]
    int*   qb = (int*)(kp + 32 * 4);     // [32]
    int*   kb = qb + TQA;                // [32]

    const bool first = (blockIdx.x < (unsigned)A0.nblk);
    AttnSide S = first ? A0 : A1;
    const int blk = first ? blockIdx.x : (blockIdx.x - A0.nblk);
    const int sp   = (S.nsplit > 1) ? (blk % S.nsplit) : 0;
    const int qblk = (S.nsplit > 1) ? (blk / S.nsplit) : blk;

    const int tid  = threadIdx.x;
    const int warp = tid >> 5;
    const int lane = tid & 31;
    const int q0   = qblk * TQA;

    for (int i = tid; i < TQA * 64; i += 256) {
        int r = i >> 6, c4 = i & 63;
        float4 v = *(const float4*)(S.Q + (size_t)(q0 + r) * DD + c4 * 4);
        v.x *= 0.0625f; v.y *= 0.0625f; v.z *= 0.0625f; v.w *= 0.0625f;
        *(float4*)(Qs + r * 256 + c4 * 4) = v;
    }
    if (tid < TQA) {
        int r = q0 + tid;
        qb[tid] = S.qbatch[r];
        qp[tid * 4 + 0] = S.qpos[r * 3 + 0];
        qp[tid * 4 + 1] = S.qpos[r * 3 + 1];
        qp[tid * 4 + 2] = S.qpos[r * 3 + 2];
    }
    __syncthreads();

    const int js = S.kstart[qb[0]];
    const int b1 = qb[TQA - 1];
    const int je = S.kstart[b1] + S.kcount[b1];

    // this split's chunk range
    const int nch = (je - js + TKA - 1) / TKA;
    const int c0 = (S.nsplit > 1) ? (sp * nch) / S.nsplit : 0;
    const int c1 = (S.nsplit > 1) ? ((sp + 1) * nch) / S.nsplit : nch;

    const int qr = warp * 4;
    float l[4] = {0.f, 0.f, 0.f, 0.f};
    float4 oa[4], ob[4];
#pragma unroll
    for (int i = 0; i < 4; ++i) { oa[i] = make_float4(0,0,0,0); ob[i] = oa[i]; }

    const float* Qb = Qs + qr * 256;
    float qpx[4], qpy[4], qpz[4];
    int qbv[4];
#pragma unroll
    for (int i = 0; i < 4; ++i) {
        qpx[i] = qp[(qr + i) * 4 + 0];
        qpy[i] = qp[(qr + i) * 4 + 1];
        qpz[i] = qp[(qr + i) * 4 + 2];
        qbv[i] = qb[qr + i];
    }

    for (int c = c0; c < c1; ++c) {
        const int j0 = js + c * TKA;
        __syncthreads();

        for (int i = tid; i < 32 * 64; i += 256) {
            int r = i >> 6, c4 = i & 63;
            int gj = j0 + r;
            float4 kv = make_float4(0,0,0,0), vv = kv;
            if (gj < je) {
                kv = *(const float4*)(S.K + (size_t)gj * DD + c4 * 4);
                vv = *(const float4*)(S.V + (size_t)gj * DD + c4 * 4);
            }
            *(float4*)(Ks + r * 256 + ((c4 ^ (r & 7)) << 2)) = kv;
            *(float4*)(Vs + r * 256 + (c4 << 2)) = vv;
        }
        if (tid < 32) {
            int gj = j0 + tid;
            if (gj < je) {
                kb[tid] = S.kbatch[gj];
                kp[tid * 4 + 0] = S.kpos[gj * 3 + 0];
                kp[tid * 4 + 1] = S.kpos[gj * 3 + 1];
                kp[tid * 4 + 2] = S.kpos[gj * 3 + 2];
            } else {
                kb[tid] = -1;
                kp[tid * 4 + 0] = 0.f; kp[tid * 4 + 1] = 0.f; kp[tid * 4 + 2] = 0.f;
            }
        }
        __syncthreads();

        // phase A: lane's key vs warp's 4 query rows; 2 accumulators per row
        const int   kbj = kb[lane];
        const float kpx = kp[lane * 4 + 0];
        const float kpy = kp[lane * 4 + 1];
        const float kpz = kp[lane * 4 + 2];
        const float* Kr = Ks + lane * 256;
        const int sw = lane & 7;

        float sA[4] = {0.f, 0.f, 0.f, 0.f};
        float sB[4] = {0.f, 0.f, 0.f, 0.f};
#pragma unroll 4
        for (int k8 = 0; k8 < 32; ++k8) {
            float4 kv0 = *(const float4*)(Kr + (((2 * k8)     ^ sw) << 2));
            float4 kv1 = *(const float4*)(Kr + (((2 * k8 + 1) ^ sw) << 2));
#pragma unroll
            for (int i = 0; i < 4; ++i) {
                float4 qv0 = *(const float4*)(Qb + i * 256 + (2 * k8) * 4);
                float4 qv1 = *(const float4*)(Qb + i * 256 + (2 * k8 + 1) * 4);
                sA[i] = fmaf(qv0.x, kv0.x, sA[i]); sA[i] = fmaf(qv0.y, kv0.y, sA[i]);
                sA[i] = fmaf(qv0.z, kv0.z, sA[i]); sA[i] = fmaf(qv0.w, kv0.w, sA[i]);
                sB[i] = fmaf(qv1.x, kv1.x, sB[i]); sB[i] = fmaf(qv1.y, kv1.y, sB[i]);
                sB[i] = fmaf(qv1.z, kv1.z, sB[i]); sB[i] = fmaf(qv1.w, kv1.w, sB[i]);
            }
        }

#pragma unroll
        for (int i = 0; i < 4; ++i) {
            float dx = qpx[i] - kpx, dy = qpy[i] - kpy, dz = qpz[i] - kpz;
            float d2 = fmaxf(fmaf(dx, dx, fmaf(dy, dy, dz * dz)), 1e-12f);
            float p = (qbv[i] == kbj)
                      ? __expf(sA[i] + sB[i] + __expf(-0.1f * sqrtf(d2))) : 0.f;
            l[i] += p;
            Ps[(qr + i) * 36 + lane] = p;
        }
        __syncwarp();

        // phase B: O += P @ V (rank-32 update, 4 rows share V loads)
#pragma unroll
        for (int j4 = 0; j4 < 8; ++j4) {
            float4 pv[4];
#pragma unroll
            for (int i = 0; i < 4; ++i)
                pv[i] = *(const float4*)(Ps + (qr + i) * 36 + j4 * 4);
#pragma unroll
            for (int jj = 0; jj < 4; ++jj) {
                const float* Vr = Vs + (j4 * 4 + jj) * 256;
                float4 va = *(const float4*)(Vr + lane * 4);
                float4 vb = *(const float4*)(Vr + 128 + lane * 4);
#pragma unroll
                for (int i = 0; i < 4; ++i) {
                    float pa = (&pv[i].x)[jj];
                    oa[i].x = fmaf(pa, va.x, oa[i].x); oa[i].y = fmaf(pa, va.y, oa[i].y);
                    oa[i].z = fmaf(pa, va.z, oa[i].z); oa[i].w = fmaf(pa, va.w, oa[i].w);
                    ob[i].x = fmaf(pa, vb.x, ob[i].x); ob[i].y = fmaf(pa, vb.y, ob[i].y);
                    ob[i].z = fmaf(pa, vb.z, ob[i].z); ob[i].w = fmaf(pa, vb.w, ob[i].w);
                }
            }
        }
    }

    // reduce per-lane sums; write (normalized or partial)
#pragma unroll
    for (int i = 0; i < 4; ++i) {
        float li = l[i];
#pragma unroll
        for (int off = 16; off; off >>= 1) li += __shfl_xor_sync(0xffffffffu, li, off);
        const int row = q0 + qr + i;
        if (S.nsplit == 1) {
            float inv = 1.0f / li;
            oa[i].x *= inv; oa[i].y *= inv; oa[i].z *= inv; oa[i].w *= inv;
            ob[i].x *= inv; ob[i].y *= inv; ob[i].z *= inv; ob[i].w *= inv;
            float* cdst = S.ctx + (size_t)row * DD;
            *(float4*)(cdst + lane * 4)       = oa[i];
            *(float4*)(cdst + 128 + lane * 4) = ob[i];
        } else {
            float* cdst = S.ctx + ((size_t)sp * S.prows + row) * DD;
            *(float4*)(cdst + lane * 4)       = oa[i];
            *(float4*)(cdst + 128 + lane * 4) = ob[i];
            if (lane == 0) S.den[sp * S.prows + row] = li;
        }
    }
}

// ---------------- merge lig split-K partials --------------------------------
__global__ __launch_bounds__(128) void norm_kernel(
    const float* __restrict__ part, const float* __restrict__ den,
    float* __restrict__ ctx)
{
    const int row = blockIdx.x * 4 + (threadIdx.x >> 5);
    const int lane = threadIdx.x & 31;
    float d = 0.f;
#pragma unroll
    for (int s = 0; s < SPLITS; ++s) d += den[s * NLIG + row];
    const float inv = 1.0f / d;
#pragma unroll
    for (int h = 0; h < 2; ++h) {
        int c = lane * 4 + h * 128;
        float4 a = make_float4(0,0,0,0);
#pragma unroll
        for (int s = 0; s < SPLITS; ++s) {
            float4 v = *(const float4*)(part + ((size_t)s * NLIG + row) * DD + c);
            a.x += v.x; a.y += v.y; a.z += v.z; a.w += v.w;
        }
        a.x *= inv; a.y *= inv; a.z *= inv; a.w *= inv;
        *(float4*)(ctx + (size_t)row * DD + c) = a;
    }
}

// ---------------- residual + bias + layernorm (both sides, one launch) ------
__global__ __launch_bounds__(128) void ln2_kernel(
    const float* __restrict__ lig, const float* __restrict__ pro,
    const float* __restrict__ tL, const float* __restrict__ tP,
    const float* __restrict__ boutL, const float* __restrict__ boutP,
    const float* __restrict__ gL, const float* __restrict__ bL,
    const float* __restrict__ gP, const float* __restrict__ bP,
    float* __restrict__ out)
{
    const int row = blockIdx.x * 4 + (threadIdx.x >> 5);
    const int lane = threadIdx.x & 31;

    const float *x, *y, *bias, *g, *bb;
    if (row < NLIG) {
        x = lig + (size_t)row * DD; y = tL + (size_t)row * DD;
        bias = boutL; g = gL; bb = bL;
    } else {
        int r = row - NLIG;
        x = pro + (size_t)r * DD; y = tP + (size_t)r * DD;
        bias = boutP; g = gP; bb = bP;
    }

    float t[8];
#pragma unroll
    for (int i = 0; i < 8; ++i) {
        int c = lane * 8 + i;
        t[i] = x[c] + y[c] + bias[c];
    }
    float s = 0.f;
#pragma unroll
    for (int i = 0; i < 8; ++i) s += t[i];
#pragma unroll
    for (int off = 16; off; off >>= 1) s += __shfl_xor_sync(0xffffffffu, s, off);
    float mu = s * (1.0f / DD);

    float v = 0.f;
#pragma unroll
    for (int i = 0; i < 8; ++i) { float d = t[i] - mu; v += d * d; }
#pragma unroll
    for (int off = 16; off; off >>= 1) v += __shfl_xor_sync(0xffffffffu, v, off);
    float r = rsqrtf(v * (1.0f / DD) + 1e-5f);

#pragma unroll
    for (int i = 0; i < 8; ++i) {
        int c = lane * 8 + i;
        out[(size_t)row * DD + c] = (t[i] - mu) * r * g[c] + bb[c];
    }
}

// ---------------- launch ----------------------------------------------------
extern "C" void kernel_launch(void* const* d_in, const int* in_sizes, int n_in,
                              void* d_out, int out_size)
{
    const float* lig      = (const float*)d_in[0];
    const float* pro      = (const float*)d_in[1];
    const float* lig_pos  = (const float*)d_in[2];
    const float* pro_pos  = (const float*)d_in[3];
    const int*   lig_batch= (const int*)  d_in[4];
    const int*   pro_batch= (const int*)  d_in[5];
    const float* Wq_lig   = (const float*)d_in[6];
    const float* Wk_pro   = (const float*)d_in[7];
    const float* Wv_pro   = (const float*)d_in[8];
    const float* Wq_pro   = (const float*)d_in[9];
    const float* Wk_lig   = (const float*)d_in[10];
    const float* Wv_lig   = (const float*)d_in[11];
    const float* Wout_lig = (const float*)d_in[12];
    const float* bout_lig = (const float*)d_in[13];
    const float* Wout_pro = (const float*)d_in[14];
    const float* bout_pro = (const float*)d_in[15];
    const float* gl       = (const float*)d_in[16];
    const float* bl       = (const float*)d_in[17];
    const float* gp       = (const float*)d_in[18];
    const float* bp       = (const float*)d_in[19];
    float* out = (float*)d_out;

    float *Q, *K, *V, *Q2, *K2, *V2, *ctxL, *ctxP, *tmpL, *tmpP, *ctxLp, *denLp;
    int *ls, *lc, *ps, *pc;
    __nv_bfloat16 *ligH, *ligL, *proH, *proL, *cLH, *cLL, *cPH, *cPL, *WH, *WL;
    cudaGetSymbolAddress((void**)&Q,    g_Q);
    cudaGetSymbolAddress((void**)&K,    g_K);
    cudaGetSymbolAddress((void**)&V,    g_V);
    cudaGetSymbolAddress((void**)&Q2,   g_Q2);
    cudaGetSymbolAddress((void**)&K2,   g_K2);
    cudaGetSymbolAddress((void**)&V2,   g_V2);
    cudaGetSymbolAddress((void**)&ctxL, g_ctxL);
    cudaGetSymbolAddress((void**)&ctxP, g_ctxP);
    cudaGetSymbolAddress((void**)&tmpL, g_tmpL);
    cudaGetSymbolAddress((void**)&tmpP, g_tmpP);
    cudaGetSymbolAddress((void**)&ctxLp,g_ctxLp);
    cudaGetSymbolAddress((void**)&denLp,g_denLp);
    cudaGetSymbolAddress((void**)&ls,   g_ls);
    cudaGetSymbolAddress((void**)&lc,   g_lc);
    cudaGetSymbolAddress((void**)&ps,   g_ps);
    cudaGetSymbolAddress((void**)&pc,   g_pc);
    cudaGetSymbolAddress((void**)&ligH, g_ligH);
    cudaGetSymbolAddress((void**)&ligL, g_ligL);
    cudaGetSymbolAddress((void**)&proH, g_proH);
    cudaGetSymbolAddress((void**)&proL, g_proL);
    cudaGetSymbolAddress((void**)&cLH,  g_cLH);
    cudaGetSymbolAddress((void**)&cLL,  g_cLL);
    cudaGetSymbolAddress((void**)&cPH,  g_cPH);
    cudaGetSymbolAddress((void**)&cPL,  g_cPL);
    cudaGetSymbolAddress((void**)&WH,   g_WH);
    cudaGetSymbolAddress((void**)&WL,   g_WL);

    cudaFuncSetAttribute(gemm_mma, cudaFuncAttributeMaxDynamicSharedMemorySize, GEMM_SMEM);
    cudaFuncSetAttribute(attn_tiled, cudaFuncAttributeMaxDynamicSharedMemorySize, ATTN_SMEM_BYTES);

    ranges_kernel<<<1, 64>>>(lig_batch, pro_batch);

    // phase-1 conversion: inputs + all 8 weights
    const float* Wsrc[8] = {Wq_lig, Wk_lig, Wv_lig, Wk_pro, Wv_pro, Wq_pro, Wout_lig, Wout_pro};
    ConvOps c1;
    c1.src[0] = lig; c1.h[0] = ligH; c1.l[0] = ligL; c1.n4[0] = NLIG * DD / 4;
    c1.src[1] = pro; c1.h[1] = proH; c1.l[1] = proL; c1.n4[1] = NPRO * DD / 4;
    for (int i = 0; i < 8; ++i) {
        c1.src[2 + i] = Wsrc[i];
        c1.h[2 + i] = WH + i * DD * DD;
        c1.l[2 + i] = WL + i * DD * DD;
        c1.n4[2 + i] = DD * DD / 4;
    }
    c1.nops = 10;
    convert_kernel<<<dim3(128, 10), 256>>>(c1);

    // all 6 QKV projections, one launch
    MmaOps gq;
    for (int i = 0; i < 3; ++i) { gq.Xh[i] = ligH; gq.Xl[i] = ligL; }
    for (int i = 3; i < 6; ++i) { gq.Xh[i] = proH; gq.Xl[i] = proL; }
    for (int i = 0; i < 6; ++i) {
        gq.Wh[i] = WH + i * DD * DD;
        gq.Wl[i] = WL + i * DD * DD;
    }
    gq.Y[0] = Q;  gq.Y[1] = K2; gq.Y[2] = V2;
    gq.Y[3] = K;  gq.Y[4] = V;  gq.Y[5] = Q2;
    gq.lig_ops = 3;
    gemm_mma<<<dim3(3 * 16 + 3 * 128, 2), 256, GEMM_SMEM>>>(gq);

    // both attention directions, one launch; lig side split-K 4 ways
    AttnSide aL, aP;
    aL.Q = Q;  aL.K = K;  aL.V = V;  aL.qpos = lig_pos; aL.kpos = pro_pos;
    aL.qbatch = lig_batch; aL.kbatch = pro_batch; aL.kstart = ps; aL.kcount = pc;
    aL.ctx = ctxLp; aL.den = denLp;
    aL.nblk = (NLIG / TQA) * SPLITS; aL.nsplit = SPLITS; aL.prows = NLIG;
    aP.Q = Q2; aP.K = K2; aP.V = V2; aP.qpos = pro_pos; aP.kpos = lig_pos;
    aP.qbatch = pro_batch; aP.kbatch = lig_batch; aP.kstart = ls; aP.kcount = lc;
    aP.ctx = ctxP; aP.den = denLp; aP.nblk = NPRO / TQA; aP.nsplit = 1; aP.prows = NPRO;
    attn_tiled<<<aL.nblk + aP.nblk, 256, ATTN_SMEM_BYTES>>>(aL, aP);

    // merge lig partials
    norm_kernel<<<NLIG / 4, 128>>>(ctxLp, denLp, ctxL);

    // phase-2 conversion: ctx
    ConvOps c2;
    c2.src[0] = ctxL; c2.h[0] = cLH; c2.l[0] = cLL; c2.n4[0] = NLIG * DD / 4;
    c2.src[1] = ctxP; c2.h[1] = cPH; c2.l[1] = cPL; c2.n4[1] = NPRO * DD / 4;
    c2.nops = 2;
    convert_kernel<<<dim3(128, 2), 256>>>(c2);

    // both output projections, one launch
    MmaOps go;
    go.Xh[0] = cLH; go.Xl[0] = cLL;
    go.Xh[1] = cPH; go.Xl[1] = cPL;
    go.Wh[0] = WH + 6 * DD * DD; go.Wl[0] = WL + 6 * DD * DD;
    go.Wh[1] = WH + 7 * DD * DD; go.Wl[1] = WL + 7 * DD * DD;
    go.Y[0] = tmpL; go.Y[1] = tmpP;
    for (int i = 2; i < 6; ++i) {
        go.Xh[i] = cLH; go.Xl[i] = cLL;
        go.Wh[i] = WH + 6 * DD * DD; go.Wl[i] = WL + 6 * DD * DD;
        go.Y[i] = tmpL;
    }
    go.lig_ops = 1;
    gemm_mma<<<dim3(16 + 128, 2), 256, GEMM_SMEM>>>(go);

    // both layernorms, one launch
    ln2_kernel<<<(NLIG + NPRO) / 4, 128>>>(lig, pro, tmpL, tmpP,
                                           bout_lig, bout_pro, gl, bl, gp, bp, out);
}

// round 9
// speedup vs baseline: 1.3462x; 1.0060x over previous
#include <cuda_runtime.h>
#include <cuda_bf16.h>
#include <cstdint>

#define DD 256
#define NLIG 2048
#define NPRO 16384
#define NB 32
#define TQA 32
#define TKA 32
#define SPLITS 4

__device__ __forceinline__ uint32_t smem_to_u32(const void* p) {
    uint32_t a;
    asm("{ .reg .u64 t; cvta.to.shared.u64 t, %1; cvt.u32.u64 %0, t; }" : "=r"(a) : "l"(p));
    return a;
}

// warp-level bf16 tensor-core MMA (compute_80+; works on plain compute_103)
#define MMA_BF16(c, a, b0v, b1v) \
    asm volatile("mma.sync.aligned.m16n8k16.row.col.f32.bf16.bf16.f32 " \
        "{%0,%1,%2,%3}, {%4,%5,%6,%7}, {%8,%9}, {%0,%1,%2,%3};" \
        : "+f"((c)[0]), "+f"((c)[1]), "+f"((c)[2]), "+f"((c)[3]) \
        : "r"((a)[0]), "r"((a)[1]), "r"((a)[2]), "r"((a)[3]), "r"(b0v), "r"(b1v))

#define LDSM_X4(r, addr) \
    asm volatile("ldmatrix.sync.aligned.m8n8.x4.shared.b16 {%0,%1,%2,%3}, [%4];" \
        : "=r"((r)[0]), "=r"((r)[1]), "=r"((r)[2]), "=r"((r)[3]) : "r"(addr))

// ---------------- scratch (static device allocation; no cudaMalloc) ---------
__device__ float g_Q  [NLIG * DD];
__device__ float g_K  [NPRO * DD];
__device__ float g_V  [NPRO * DD];
__device__ float g_Q2 [NPRO * DD];
__device__ float g_K2 [NLIG * DD];
__device__ float g_V2 [NLIG * DD];
__device__ float g_ctxL[NLIG * DD];
__device__ float g_ctxP[NPRO * DD];
__device__ float g_tmpL[NLIG * DD];
__device__ float g_tmpP[NPRO * DD];
__device__ float g_ctxLp[SPLITS * NLIG * DD];   // lig split-K partials
__device__ float g_denLp[SPLITS * NLIG];        // lig split-K denominators
__device__ int g_ls[NB], g_lc[NB], g_ps[NB], g_pc[NB];

// pre-split bf16 hi/lo buffers
__device__ __nv_bfloat16 g_ligH[NLIG * DD], g_ligL[NLIG * DD];
__device__ __nv_bfloat16 g_proH[NPRO * DD], g_proL[NPRO * DD];
__device__ __nv_bfloat16 g_cLH [NLIG * DD], g_cLL [NLIG * DD];
__device__ __nv_bfloat16 g_cPH [NPRO * DD], g_cPL [NPRO * DD];
__device__ __nv_bfloat16 g_WH  [8 * DD * DD], g_WL [8 * DD * DD];

// ---------------- fp32 -> bf16 hi/lo split conversion -----------------------
__device__ __forceinline__ void split2(float a, float b, uint32_t& hi, uint32_t& lo)
{
    __nv_bfloat16 ha = __float2bfloat16(a), hb = __float2bfloat16(b);
    __nv_bfloat162 hp = __halves2bfloat162(ha, hb);
    hi = *reinterpret_cast<uint32_t*>(&hp);
    float la = a - __bfloat162float(ha);
    float lb = b - __bfloat162float(hb);
    __nv_bfloat162 lp = __floats2bfloat162_rn(la, lb);
    lo = *reinterpret_cast<uint32_t*>(&lp);
}

struct ConvOps {
    const float* src[10];
    __nv_bfloat16 *h[10], *l[10];
    int n4[10];
    int nops;
};

__global__ __launch_bounds__(256) void convert_kernel(ConvOps C)
{
    const int op = blockIdx.y;
    const float* __restrict__ s = C.src[op];
    __nv_bfloat16* __restrict__ h = C.h[op];
    __nv_bfloat16* __restrict__ l = C.l[op];
    const int n4 = C.n4[op];
    for (int i = blockIdx.x * 256 + threadIdx.x; i < n4; i += gridDim.x * 256) {
        float4 f = *(const float4*)(s + i * 4);
        uint32_t h0, l0, h1, l1;
        split2(f.x, f.y, h0, l0);
        split2(f.z, f.w, h1, l1);
        *(uint2*)(h + i * 4) = make_uint2(h0, h1);
        *(uint2*)(l + i * 4) = make_uint2(l0, l1);
    }
}

// ---------------- per-batch ranges via binary search (batch ids sorted) -----
__global__ void ranges_kernel(const int* __restrict__ lb, const int* __restrict__ pb)
{
    int t = threadIdx.x;
    if (t < NB) {
        int b = t;
        int lo = 0, hi = NLIG;
        while (lo < hi) { int mid = (lo + hi) >> 1; if (lb[mid] < b) lo = mid + 1; else hi = mid; }
        int s = lo; hi = NLIG;
        while (lo < hi) { int mid = (lo + hi) >> 1; if (lb[mid] <= b) lo = mid + 1; else hi = mid; }
        g_ls[b] = s; g_lc[b] = lo - s;
    } else if (t < 2 * NB) {
        int b = t - NB;
        int lo = 0, hi = NPRO;
        while (lo < hi) { int mid = (lo + hi) >> 1; if (pb[mid] < b) lo = mid + 1; else hi = mid; }
        int s = lo; hi = NPRO;
        while (lo < hi) { int mid = (lo + hi) >> 1; if (pb[mid] <= b) lo = mid + 1; else hi = mid; }
        g_ps[b] = s; g_pc[b] = lo - s;
    }
}

// ============ split-bf16 mma.sync GEMM (pre-split operands) =================
struct MmaOps {
    const __nv_bfloat16 *Xh[6], *Xl[6], *Wh[6], *Wl[6];
    float* Y[6];
    int lig_ops;    // first lig_ops ops have 16 row-tiles, remainder 128
};

#define GEMM_SMEM 65536

__global__ __launch_bounds__(256, 2) void gemm_mma(MmaOps P)
{
    extern __shared__ char smc[];
    const uint32_t sb = smem_to_u32(smc);

    const int bx = blockIdx.x;
    const int ligregion = P.lig_ops * 16;
    int op, mt;
    if (bx < ligregion) { op = bx >> 4; mt = bx & 15; }
    else { int r = bx - ligregion; op = P.lig_ops + (r >> 7); mt = r & 127; }
    const __nv_bfloat16* __restrict__ Xh = P.Xh[op];
    const __nv_bfloat16* __restrict__ Xl = P.Xl[op];
    const __nv_bfloat16* __restrict__ Wh = P.Wh[op];
    const __nv_bfloat16* __restrict__ Wl = P.Wl[op];
    float* __restrict__ Y = P.Y[op];
    const int m0 = mt * 128;
    const int n0 = blockIdx.y * 128;

    const int tid = threadIdx.x, lane = tid & 31, wid = tid >> 5;
    const int warpM = wid & 3, warpN = wid >> 2;
    const int sub = lane >> 3, r8 = lane & 7;

    float acc[2][8][4];
#pragma unroll
    for (int i = 0; i < 2; ++i)
#pragma unroll
        for (int j = 0; j < 8; ++j)
#pragma unroll
            for (int k = 0; k < 4; ++k) acc[i][j][k] = 0.f;

    for (int kc = 0; kc < 4; ++kc) {
#pragma unroll
        for (int it = 0; it < 4; ++it) {
            int idx = tid + it * 256;
            int r = idx >> 3, c8 = idx & 7;
            int byte = (r * 128 + c8 * 16) ^ ((r & 7) << 4);
            size_t goff = (size_t)(m0 + r) * DD + kc * 64 + c8 * 8;
            size_t woff = (size_t)(n0 + r) * DD + kc * 64 + c8 * 8;
            *(uint4*)(smc + byte)         = *(const uint4*)(Xh + goff);
            *(uint4*)(smc + 16384 + byte) = *(const uint4*)(Xl + goff);
            *(uint4*)(smc + 32768 + byte) = *(const uint4*)(Wh + woff);
            *(uint4*)(smc + 49152 + byte) = *(const uint4*)(Wl + woff);
        }
        __syncthreads();

#pragma unroll
        for (int k16 = 0; k16 < 4; ++k16) {
            uint32_t a_hi[2][4], a_lo[2][4];
#pragma unroll
            for (int mt2 = 0; mt2 < 2; ++mt2) {
                int row = warpM * 32 + mt2 * 16 + (sub & 1) * 8 + r8;
                int k8  = k16 * 2 + (sub >> 1);
                uint32_t ad = sb + ((row * 128 + k8 * 16) ^ ((row & 7) << 4));
                LDSM_X4(a_hi[mt2], ad);
                LDSM_X4(a_lo[mt2], ad + 16384);
            }
#pragma unroll
            for (int np = 0; np < 4; ++np) {
                int nrow = warpN * 64 + np * 16 + (sub >> 1) * 8 + r8;
                int k8   = k16 * 2 + (sub & 1);
                uint32_t bd = sb + 32768 + ((nrow * 128 + k8 * 16) ^ ((nrow & 7) << 4));
                uint32_t b_hi[4], b_lo[4];
                LDSM_X4(b_hi, bd);
                LDSM_X4(b_lo, bd + 16384);
#pragma unroll
                for (int mt2 = 0; mt2 < 2; ++mt2) {
                    MMA_BF16(acc[mt2][np * 2],     a_hi[mt2], b_hi[0], b_hi[1]);
                    MMA_BF16(acc[mt2][np * 2 + 1], a_hi[mt2], b_hi[2], b_hi[3]);
                    MMA_BF16(acc[mt2][np * 2],     a_hi[mt2], b_lo[0], b_lo[1]);
                    MMA_BF16(acc[mt2][np * 2 + 1], a_hi[mt2], b_lo[2], b_lo[3]);
                    MMA_BF16(acc[mt2][np * 2],     a_lo[mt2], b_hi[0], b_hi[1]);
                    MMA_BF16(acc[mt2][np * 2 + 1], a_lo[mt2], b_hi[2], b_hi[3]);
                }
            }
        }
        __syncthreads();
    }

    const int t4 = lane >> 2, q = lane & 3;
#pragma unroll
    for (int mt2 = 0; mt2 < 2; ++mt2) {
#pragma unroll
        for (int nt = 0; nt < 8; ++nt) {
            float* yr = Y + (size_t)(m0 + warpM * 32 + mt2 * 16 + t4) * DD
                          + n0 + warpN * 64 + nt * 8 + q * 2;
            *(float2*)yr            = make_float2(acc[mt2][nt][0], acc[mt2][nt][1]);
            *(float2*)(yr + 8 * DD) = make_float2(acc[mt2][nt][2], acc[mt2][nt][3]);
        }
    }
}

// ======== tiled flash attention, block-diagonal, no-max, split-K ============
// TQA=32 queries/CTA, 8 warps x 4 query rows. Side 0 (lig) splits its key
// range into SPLITS sub-blocks writing additive partials (no-max softmax is
// linear in (sum pV, sum p)); side 1 (pro) normalizes in-kernel.

struct AttnSide {
    const float *Q, *K, *V, *qpos, *kpos;
    const int *qbatch, *kbatch, *kstart, *kcount;
    float* ctx;     // nsplit==1: final ctx; else partials [nsplit][prows][DD]
    float* den;     // nsplit>1: [nsplit][prows]
    int nblk;
    int nsplit;
    int prows;
};

#define ATTN_SMEM_FLOATS (TQA*256 + 32*256 + 32*256 + TQA*36 + TQA*4 + 32*4 + TQA + 32)
#define ATTN_SMEM_BYTES  (ATTN_SMEM_FLOATS * 4)

__global__ __launch_bounds__(256, 2) void attn_tiled(AttnSide A0, AttnSide A1)
{
    extern __shared__ float sm[];
    float* Qs = sm;                      // [32][256]
    float* Ks = Qs + TQA * 256;          // [32][256] (col4 xor-swizzled by row&7)
    float* Vs = Ks + 32 * 256;           // [32][256]
    float* Ps = Vs + 32 * 256;           // [32][36]
    float* qp = Ps + TQA * 36;           // [32][4]
    float* kp = qp + TQA * 4;            // [32][4]
    int*   qb = (int*)(kp + 32 * 4);     // [32]
    int*   kb = qb + TQA;                // [32]

    const bool first = (blockIdx.x < (unsigned)A0.nblk);
    AttnSide S = first ? A0 : A1;
    const int blk = first ? blockIdx.x : (blockIdx.x - A0.nblk);
    const int sp   = (S.nsplit > 1) ? (blk % S.nsplit) : 0;
    const int qblk = (S.nsplit > 1) ? (blk / S.nsplit) : blk;

    const int tid  = threadIdx.x;
    const int warp = tid >> 5;
    const int lane = tid & 31;
    const int q0   = qblk * TQA;

    for (int i = tid; i < TQA * 64; i += 256) {
        int r = i >> 6, c4 = i & 63;
        float4 v = *(const float4*)(S.Q + (size_t)(q0 + r) * DD + c4 * 4);
        v.x *= 0.0625f; v.y *= 0.0625f; v.z *= 0.0625f; v.w *= 0.0625f;
        *(float4*)(Qs + r * 256 + c4 * 4) = v;
    }
    if (tid < TQA) {
        int r = q0 + tid;
        qb[tid] = S.qbatch[r];
        qp[tid * 4 + 0] = S.qpos[r * 3 + 0];
        qp[tid * 4 + 1] = S.qpos[r * 3 + 1];
        qp[tid * 4 + 2] = S.qpos[r * 3 + 2];
    }
    __syncthreads();

    const int js = S.kstart[qb[0]];
    const int b1 = qb[TQA - 1];
    const int je = S.kstart[b1] + S.kcount[b1];

    // this split's chunk range
    const int nch = (je - js + TKA - 1) / TKA;
    const int c0 = (S.nsplit > 1) ? (sp * nch) / S.nsplit : 0;
    const int c1 = (S.nsplit > 1) ? ((sp + 1) * nch) / S.nsplit : nch;

    const int qr = warp * 4;
    float l[4] = {0.f, 0.f, 0.f, 0.f};
    float4 oa[4], ob[4];
#pragma unroll
    for (int i = 0; i < 4; ++i) { oa[i] = make_float4(0,0,0,0); ob[i] = oa[i]; }

    const float* Qb = Qs + qr * 256;
    float qpx[4], qpy[4], qpz[4];
    int qbv[4];
#pragma unroll
    for (int i = 0; i < 4; ++i) {
        qpx[i] = qp[(qr + i) * 4 + 0];
        qpy[i] = qp[(qr + i) * 4 + 1];
        qpz[i] = qp[(qr + i) * 4 + 2];
        qbv[i] = qb[qr + i];
    }

    for (int c = c0; c < c1; ++c) {
        const int j0 = js + c * TKA;
        __syncthreads();

        for (int i = tid; i < 32 * 64; i += 256) {
            int r = i >> 6, c4 = i & 63;
            int gj = j0 + r;
            float4 kv = make_float4(0,0,0,0), vv = kv;
            if (gj < je) {
                kv = *(const float4*)(S.K + (size_t)gj * DD + c4 * 4);
                vv = *(const float4*)(S.V + (size_t)gj * DD + c4 * 4);
            }
            *(float4*)(Ks + r * 256 + ((c4 ^ (r & 7)) << 2)) = kv;
            *(float4*)(Vs + r * 256 + (c4 << 2)) = vv;
        }
        if (tid < 32) {
            int gj = j0 + tid;
            if (gj < je) {
                kb[tid] = S.kbatch[gj];
                kp[tid * 4 + 0] = S.kpos[gj * 3 + 0];
                kp[tid * 4 + 1] = S.kpos[gj * 3 + 1];
                kp[tid * 4 + 2] = S.kpos[gj * 3 + 2];
            } else {
                kb[tid] = -1;
                kp[tid * 4 + 0] = 0.f; kp[tid * 4 + 1] = 0.f; kp[tid * 4 + 2] = 0.f;
            }
        }
        __syncthreads();

        // phase A: lane's key vs warp's 4 query rows; 2 accumulators per row
        const int   kbj = kb[lane];
        const float kpx = kp[lane * 4 + 0];
        const float kpy = kp[lane * 4 + 1];
        const float kpz = kp[lane * 4 + 2];
        const float* Kr = Ks + lane * 256;
        const int sw = lane & 7;

        float sA[4] = {0.f, 0.f, 0.f, 0.f};
        float sB[4] = {0.f, 0.f, 0.f, 0.f};
#pragma unroll 4
        for (int k8 = 0; k8 < 32; ++k8) {
            float4 kv0 = *(const float4*)(Kr + (((2 * k8)     ^ sw) << 2));
            float4 kv1 = *(const float4*)(Kr + (((2 * k8 + 1) ^ sw) << 2));
#pragma unroll
            for (int i = 0; i < 4; ++i) {
                float4 qv0 = *(const float4*)(Qb + i * 256 + (2 * k8) * 4);
                float4 qv1 = *(const float4*)(Qb + i * 256 + (2 * k8 + 1) * 4);
                sA[i] = fmaf(qv0.x, kv0.x, sA[i]); sA[i] = fmaf(qv0.y, kv0.y, sA[i]);
                sA[i] = fmaf(qv0.z, kv0.z, sA[i]); sA[i] = fmaf(qv0.w, kv0.w, sA[i]);
                sB[i] = fmaf(qv1.x, kv1.x, sB[i]); sB[i] = fmaf(qv1.y, kv1.y, sB[i]);
                sB[i] = fmaf(qv1.z, kv1.z, sB[i]); sB[i] = fmaf(qv1.w, kv1.w, sB[i]);
            }
        }

#pragma unroll
        for (int i = 0; i < 4; ++i) {
            float dx = qpx[i] - kpx, dy = qpy[i] - kpy, dz = qpz[i] - kpz;
            float d2 = fmaxf(fmaf(dx, dx, fmaf(dy, dy, dz * dz)), 1e-12f);
            float p = (qbv[i] == kbj)
                      ? __expf(sA[i] + sB[i] + __expf(-0.1f * sqrtf(d2))) : 0.f;
            l[i] += p;
            Ps[(qr + i) * 36 + lane] = p;
        }
        __syncwarp();

        // phase B: O += P @ V (rank-32 update, 4 rows share V loads)
#pragma unroll
        for (int j4 = 0; j4 < 8; ++j4) {
            float4 pv[4];
#pragma unroll
            for (int i = 0; i < 4; ++i)
                pv[i] = *(const float4*)(Ps + (qr + i) * 36 + j4 * 4);
#pragma unroll
            for (int jj = 0; jj < 4; ++jj) {
                const float* Vr = Vs + (j4 * 4 + jj) * 256;
                float4 va = *(const float4*)(Vr + lane * 4);
                float4 vb = *(const float4*)(Vr + 128 + lane * 4);
#pragma unroll
                for (int i = 0; i < 4; ++i) {
                    float pa = (&pv[i].x)[jj];
                    oa[i].x = fmaf(pa, va.x, oa[i].x); oa[i].y = fmaf(pa, va.y, oa[i].y);
                    oa[i].z = fmaf(pa, va.z, oa[i].z); oa[i].w = fmaf(pa, va.w, oa[i].w);
                    ob[i].x = fmaf(pa, vb.x, ob[i].x); ob[i].y = fmaf(pa, vb.y, ob[i].y);
                    ob[i].z = fmaf(pa, vb.z, ob[i].z); ob[i].w = fmaf(pa, vb.w, ob[i].w);
                }
            }
        }
    }

    // reduce per-lane sums; write (normalized or partial)
#pragma unroll
    for (int i = 0; i < 4; ++i) {
        float li = l[i];
#pragma unroll
        for (int off = 16; off; off >>= 1) li += __shfl_xor_sync(0xffffffffu, li, off);
        const int row = q0 + qr + i;
        if (S.nsplit == 1) {
            float inv = 1.0f / li;
            oa[i].x *= inv; oa[i].y *= inv; oa[i].z *= inv; oa[i].w *= inv;
            ob[i].x *= inv; ob[i].y *= inv; ob[i].z *= inv; ob[i].w *= inv;
            float* cdst = S.ctx + (size_t)row * DD;
            *(float4*)(cdst + lane * 4)       = oa[i];
            *(float4*)(cdst + 128 + lane * 4) = ob[i];
        } else {
            float* cdst = S.ctx + ((size_t)sp * S.prows + row) * DD;
            *(float4*)(cdst + lane * 4)       = oa[i];
            *(float4*)(cdst + 128 + lane * 4) = ob[i];
            if (lane == 0) S.den[sp * S.prows + row] = li;
        }
    }
}

// ---------------- merge lig split-K partials --------------------------------
__global__ __launch_bounds__(128) void norm_kernel(
    const float* __restrict__ part, const float* __restrict__ den,
    float* __restrict__ ctx)
{
    const int row = blockIdx.x * 4 + (threadIdx.x >> 5);
    const int lane = threadIdx.x & 31;
    float d = 0.f;
#pragma unroll
    for (int s = 0; s < SPLITS; ++s) d += den[s * NLIG + row];
    const float inv = 1.0f / d;
#pragma unroll
    for (int h = 0; h < 2; ++h) {
        int c = lane * 4 + h * 128;
        float4 a = make_float4(0,0,0,0);
#pragma unroll
        for (int s = 0; s < SPLITS; ++s) {
            float4 v = *(const float4*)(part + ((size_t)s * NLIG + row) * DD + c);
            a.x += v.x; a.y += v.y; a.z += v.z; a.w += v.w;
        }
        a.x *= inv; a.y *= inv; a.z *= inv; a.w *= inv;
        *(float4*)(ctx + (size_t)row * DD + c) = a;
    }
}

// ---------------- residual + bias + layernorm (both sides, one launch) ------
__global__ __launch_bounds__(128) void ln2_kernel(
    const float* __restrict__ lig, const float* __restrict__ pro,
    const float* __restrict__ tL, const float* __restrict__ tP,
    const float* __restrict__ boutL, const float* __restrict__ boutP,
    const float* __restrict__ gL, const float* __restrict__ bL,
    const float* __restrict__ gP, const float* __restrict__ bP,
    float* __restrict__ out)
{
    const int row = blockIdx.x * 4 + (threadIdx.x >> 5);
    const int lane = threadIdx.x & 31;

    const float *x, *y, *bias, *g, *bb;
    if (row < NLIG) {
        x = lig + (size_t)row * DD; y = tL + (size_t)row * DD;
        bias = boutL; g = gL; bb = bL;
    } else {
        int r = row - NLIG;
        x = pro + (size_t)r * DD; y = tP + (size_t)r * DD;
        bias = boutP; g = gP; bb = bP;
    }

    float t[8];
#pragma unroll
    for (int i = 0; i < 8; ++i) {
        int c = lane * 8 + i;
        t[i] = x[c] + y[c] + bias[c];
    }
    float s = 0.f;
#pragma unroll
    for (int i = 0; i < 8; ++i) s += t[i];
#pragma unroll
    for (int off = 16; off; off >>= 1) s += __shfl_xor_sync(0xffffffffu, s, off);
    float mu = s * (1.0f / DD);

    float v = 0.f;
#pragma unroll
    for (int i = 0; i < 8; ++i) { float d = t[i] - mu; v += d * d; }
#pragma unroll
    for (int off = 16; off; off >>= 1) v += __shfl_xor_sync(0xffffffffu, v, off);
    float r = rsqrtf(v * (1.0f / DD) + 1e-5f);

#pragma unroll
    for (int i = 0; i < 8; ++i) {
        int c = lane * 8 + i;
        out[(size_t)row * DD + c] = (t[i] - mu) * r * g[c] + bb[c];
    }
}

// ---------------- launch ----------------------------------------------------
extern "C" void kernel_launch(void* const* d_in, const int* in_sizes, int n_in,
                              void* d_out, int out_size)
{
    const float* lig      = (const float*)d_in[0];
    const float* pro      = (const float*)d_in[1];
    const float* lig_pos  = (const float*)d_in[2];
    const float* pro_pos  = (const float*)d_in[3];
    const int*   lig_batch= (const int*)  d_in[4];
    const int*   pro_batch= (const int*)  d_in[5];
    const float* Wq_lig   = (const float*)d_in[6];
    const float* Wk_pro   = (const float*)d_in[7];
    const float* Wv_pro   = (const float*)d_in[8];
    const float* Wq_pro   = (const float*)d_in[9];
    const float* Wk_lig   = (const float*)d_in[10];
    const float* Wv_lig   = (const float*)d_in[11];
    const float* Wout_lig = (const float*)d_in[12];
    const float* bout_lig = (const float*)d_in[13];
    const float* Wout_pro = (const float*)d_in[14];
    const float* bout_pro = (const float*)d_in[15];
    const float* gl       = (const float*)d_in[16];
    const float* bl       = (const float*)d_in[17];
    const float* gp       = (const float*)d_in[18];
    const float* bp       = (const float*)d_in[19];
    float* out = (float*)d_out;

    float *Q, *K, *V, *Q2, *K2, *V2, *ctxL, *ctxP, *tmpL, *tmpP, *ctxLp, *denLp;
    int *ls, *lc, *ps, *pc;
    __nv_bfloat16 *ligH, *ligL, *proH, *proL, *cLH, *cLL, *cPH, *cPL, *WH, *WL;
    cudaGetSymbolAddress((void**)&Q,    g_Q);
    cudaGetSymbolAddress((void**)&K,    g_K);
    cudaGetSymbolAddress((void**)&V,    g_V);
    cudaGetSymbolAddress((void**)&Q2,   g_Q2);
    cudaGetSymbolAddress((void**)&K2,   g_K2);
    cudaGetSymbolAddress((void**)&V2,   g_V2);
    cudaGetSymbolAddress((void**)&ctxL, g_ctxL);
    cudaGetSymbolAddress((void**)&ctxP, g_ctxP);
    cudaGetSymbolAddress((void**)&tmpL, g_tmpL);
    cudaGetSymbolAddress((void**)&tmpP, g_tmpP);
    cudaGetSymbolAddress((void**)&ctxLp,g_ctxLp);
    cudaGetSymbolAddress((void**)&denLp,g_denLp);
    cudaGetSymbolAddress((void**)&ls,   g_ls);
    cudaGetSymbolAddress((void**)&lc,   g_lc);
    cudaGetSymbolAddress((void**)&ps,   g_ps);
    cudaGetSymbolAddress((void**)&pc,   g_pc);
    cudaGetSymbolAddress((void**)&ligH, g_ligH);
    cudaGetSymbolAddress((void**)&ligL, g_ligL);
    cudaGetSymbolAddress((void**)&proH, g_proH);
    cudaGetSymbolAddress((void**)&proL, g_proL);
    cudaGetSymbolAddress((void**)&cLH,  g_cLH);
    cudaGetSymbolAddress((void**)&cLL,  g_cLL);
    cudaGetSymbolAddress((void**)&cPH,  g_cPH);
    cudaGetSymbolAddress((void**)&cPL,  g_cPL);
    cudaGetSymbolAddress((void**)&WH,   g_WH);
    cudaGetSymbolAddress((void**)&WL,   g_WL);

    cudaFuncSetAttribute(gemm_mma, cudaFuncAttributeMaxDynamicSharedMemorySize, GEMM_SMEM);
    cudaFuncSetAttribute(attn_tiled, cudaFuncAttributeMaxDynamicSharedMemorySize, ATTN_SMEM_BYTES);

    ranges_kernel<<<1, 64>>>(lig_batch, pro_batch);

    // phase-1 conversion: inputs + all 8 weights
    const float* Wsrc[8] = {Wq_lig, Wk_lig, Wv_lig, Wk_pro, Wv_pro, Wq_pro, Wout_lig, Wout_pro};
    ConvOps c1;
    c1.src[0] = lig; c1.h[0] = ligH; c1.l[0] = ligL; c1.n4[0] = NLIG * DD / 4;
    c1.src[1] = pro; c1.h[1] = proH; c1.l[1] = proL; c1.n4[1] = NPRO * DD / 4;
    for (int i = 0; i < 8; ++i) {
        c1.src[2 + i] = Wsrc[i];
        c1.h[2 + i] = WH + i * DD * DD;
        c1.l[2 + i] = WL + i * DD * DD;
        c1.n4[2 + i] = DD * DD / 4;
    }
    c1.nops = 10;
    convert_kernel<<<dim3(128, 10), 256>>>(c1);

    // all 6 QKV projections, one launch
    MmaOps gq;
    for (int i = 0; i < 3; ++i) { gq.Xh[i] = ligH; gq.Xl[i] = ligL; }
    for (int i = 3; i < 6; ++i) { gq.Xh[i] = proH; gq.Xl[i] = proL; }
    for (int i = 0; i < 6; ++i) {
        gq.Wh[i] = WH + i * DD * DD;
        gq.Wl[i] = WL + i * DD * DD;
    }
    gq.Y[0] = Q;  gq.Y[1] = K2; gq.Y[2] = V2;
    gq.Y[3] = K;  gq.Y[4] = V;  gq.Y[5] = Q2;
    gq.lig_ops = 3;
    gemm_mma<<<dim3(3 * 16 + 3 * 128, 2), 256, GEMM_SMEM>>>(gq);

    // both attention directions, one launch; lig side split-K 4 ways
    AttnSide aL, aP;
    aL.Q = Q;  aL.K = K;  aL.V = V;  aL.qpos = lig_pos; aL.kpos = pro_pos;
    aL.qbatch = lig_batch; aL.kbatch = pro_batch; aL.kstart = ps; aL.kcount = pc;
    aL.ctx = ctxLp; aL.den = denLp;
    aL.nblk = (NLIG / TQA) * SPLITS; aL.nsplit = SPLITS; aL.prows = NLIG;
    aP.Q = Q2; aP.K = K2; aP.V = V2; aP.qpos = pro_pos; aP.kpos = lig_pos;
    aP.qbatch = pro_batch; aP.kbatch = lig_batch; aP.kstart = ls; aP.kcount = lc;
    aP.ctx = ctxP; aP.den = denLp; aP.nblk = NPRO / TQA; aP.nsplit = 1; aP.prows = NPRO;
    attn_tiled<<<aL.nblk + aP.nblk, 256, ATTN_SMEM_BYTES>>>(aL, aP);

    // merge lig partials
    norm_kernel<<<NLIG / 4, 128>>>(ctxLp, denLp, ctxL);

    // phase-2 conversion: ctx
    ConvOps c2;
    c2.src[0] = ctxL; c2.h[0] = cLH; c2.l[0] = cLL; c2.n4[0] = NLIG * DD / 4;
    c2.src[1] = ctxP; c2.h[1] = cPH; c2.l[1] = cPL; c2.n4[1] = NPRO * DD / 4;
    c2.nops = 2;
    convert_kernel<<<dim3(128, 2), 256>>>(c2);

    // both output projections, one launch
    MmaOps go;
    go.Xh[0] = cLH; go.Xl[0] = cLL;
    go.Xh[1] = cPH; go.Xl[1] = cPL;
    go.Wh[0] = WH + 6 * DD * DD; go.Wl[0] = WL + 6 * DD * DD;
    go.Wh[1] = WH + 7 * DD * DD; go.Wl[1] = WL + 7 * DD * DD;
    go.Y[0] = tmpL; go.Y[1] = tmpP;
    for (int i = 2; i < 6; ++i) {
        go.Xh[i] = cLH; go.Xl[i] = cLL;
        go.Wh[i] = WH + 6 * DD * DD; go.Wl[i] = WL + 6 * DD * DD;
        go.Y[i] = tmpL;
    }
    go.lig_ops = 1;
    gemm_mma<<<dim3(16 + 128, 2), 256, GEMM_SMEM>>>(go);

    // both layernorms, one launch
    ln2_kernel<<<(NLIG + NPRO) / 4, 128>>>(lig, pro, tmpL, tmpP,
                                           bout_lig, bout_pro, gl, bl, gp, bp, out);
}